// round 2
// baseline (speedup 1.0000x reference)
#include <cuda_runtime.h>
#include <cuda_bf16.h>
#include <cstdint>
#include <cstddef>

// Problem dims (fixed)
#define BB 16
#define SS 2048
#define DD 256
#define GD 1024      // 4*D
#define LL 4
#define CS 8         // cluster size (CTAs per batch recurrence)
#define SLICE 32     // D / CS

// ---------------- scratch (static device globals; no allocations) ----------------
__device__ float g_h [BB * SS * DD];   // hidden / residual stream  (32 MB)
__device__ float g_xn[BB * SS * DD];   // layernormed activations   (32 MB)
__device__ float g_gx[(size_t)BB * SS * GD];  // gate preactivations (128 MB)

// ---------------- f32x2 packed helpers ----------------
__device__ __forceinline__ unsigned long long pack2f(float lo, float hi) {
    unsigned long long r;
    asm("mov.b64 %0, {%1, %2};" : "=l"(r) : "f"(lo), "f"(hi));
    return r;
}
__device__ __forceinline__ float2 unpack2f(unsigned long long v) {
    float2 r;
    asm("mov.b64 {%0, %1}, %2;" : "=f"(r.x), "=f"(r.y) : "l"(v));
    return r;
}
__device__ __forceinline__ unsigned long long ffma2(unsigned long long a,
                                                    unsigned long long b,
                                                    unsigned long long c) {
    unsigned long long d;
    asm("fma.rn.f32x2 %0, %1, %2, %3;" : "=l"(d) : "l"(a), "l"(b), "l"(c));
    return d;
}
__device__ __forceinline__ uint32_t smem_u32(const void* p) {
    uint32_t a;
    asm("{ .reg .u64 t; cvta.to.shared.u64 t, %1; cvt.u32.u64 %0, t; }"
        : "=r"(a) : "l"(p));
    return a;
}
#define CLUSTER_SYNC() do {                                          \
    asm volatile("barrier.cluster.arrive.aligned;" ::: "memory");    \
    asm volatile("barrier.cluster.wait.aligned;"   ::: "memory");    \
} while (0)

// ---------------- 1) embedding: h = concat(x, tf) @ in_W + in_b ----------------
__global__ __launch_bounds__(DD) void embed_kernel(
    const float* __restrict__ x, const float* __restrict__ tf,
    const float* __restrict__ inW, const float* __restrict__ inb)
{
    int row = blockIdx.x;            // b*S + s
    int d   = threadIdx.x;           // 0..255
    float xv  = x[row];
    float acc = inb[d] + xv * inW[d];
#pragma unroll
    for (int f = 0; f < 6; ++f)
        acc += tf[row * 6 + f] * inW[(1 + f) * DD + d];
    g_h[(size_t)row * DD + d] = acc;
}

// ---------------- 2) layernorm: xn = LN(h)*g + b (one warp per row) ----------------
__global__ __launch_bounds__(256) void ln_kernel(
    const float* __restrict__ gam, const float* __restrict__ bet)
{
    int warp = (blockIdx.x * blockDim.x + threadIdx.x) >> 5;
    int lane = threadIdx.x & 31;
    if (warp >= BB * SS) return;
    const float* row = g_h + (size_t)warp * DD;
    float v[8], s = 0.f, s2 = 0.f;
#pragma unroll
    for (int i = 0; i < 8; ++i) {
        v[i] = row[lane + i * 32];
        s  += v[i];
        s2 += v[i] * v[i];
    }
#pragma unroll
    for (int o = 16; o; o >>= 1) {
        s  += __shfl_xor_sync(0xffffffffu, s,  o);
        s2 += __shfl_xor_sync(0xffffffffu, s2, o);
    }
    float mu  = s * (1.f / DD);
    float var = s2 * (1.f / DD) - mu * mu;
    float rs  = rsqrtf(var + 1e-5f);
    float* orow = g_xn + (size_t)warp * DD;
#pragma unroll
    for (int i = 0; i < 8; ++i) {
        int d = lane + i * 32;
        orow[d] = (v[i] - mu) * rs * gam[d] + bet[d];
    }
}

// ---------------- 3) gx GEMM: gx = xn @ Wx_l + bg_l  (M=32768, N=1024, K=256) ----------------
#define GBM 128
#define GBN 128
#define GBK 16
__global__ __launch_bounds__(256) void gemm_kernel(
    const float* __restrict__ Wx_l, const float* __restrict__ bg_l)
{
    __shared__ __align__(16) float As[GBK][GBM];
    __shared__ __align__(16) float Bs[GBK][GBN];
    int tid = threadIdx.x;
    int m0  = blockIdx.y * GBM;
    int n0  = blockIdx.x * GBN;
    int ty = tid >> 4, tx = tid & 15;
    int rbase = ty * 8, cbase = tx * 8;

    unsigned long long acc[8][4];
#pragma unroll
    for (int i = 0; i < 8; ++i)
#pragma unroll
        for (int p = 0; p < 4; ++p) acc[i][p] = 0ull;

    for (int k0 = 0; k0 < DD; k0 += GBK) {
        __syncthreads();
#pragma unroll
        for (int q = 0; q < 2; ++q) {
            int f = tid * 2 + q;
            int arow = f >> 2, ac4 = f & 3;
            float4 av = *reinterpret_cast<const float4*>(
                &g_xn[(size_t)(m0 + arow) * DD + k0 + ac4 * 4]);
            As[ac4 * 4 + 0][arow] = av.x;
            As[ac4 * 4 + 1][arow] = av.y;
            As[ac4 * 4 + 2][arow] = av.z;
            As[ac4 * 4 + 3][arow] = av.w;
            int brow = f >> 5, bc4 = f & 31;
            *reinterpret_cast<float4*>(&Bs[brow][bc4 * 4]) =
                *reinterpret_cast<const float4*>(
                    &Wx_l[(size_t)(k0 + brow) * GD + n0 + bc4 * 4]);
        }
        __syncthreads();
#pragma unroll
        for (int kk = 0; kk < GBK; ++kk) {
            float4 a0 = *reinterpret_cast<const float4*>(&As[kk][rbase]);
            float4 a1 = *reinterpret_cast<const float4*>(&As[kk][rbase + 4]);
            float4 b0 = *reinterpret_cast<const float4*>(&Bs[kk][cbase]);
            float4 b1 = *reinterpret_cast<const float4*>(&Bs[kk][cbase + 4]);
            unsigned long long bp[4] = { pack2f(b0.x, b0.y), pack2f(b0.z, b0.w),
                                         pack2f(b1.x, b1.y), pack2f(b1.z, b1.w) };
            float aa[8] = { a0.x, a0.y, a0.z, a0.w, a1.x, a1.y, a1.z, a1.w };
#pragma unroll
            for (int i = 0; i < 8; ++i) {
                unsigned long long ad = pack2f(aa[i], aa[i]);
#pragma unroll
                for (int p = 0; p < 4; ++p) acc[i][p] = ffma2(ad, bp[p], acc[i][p]);
            }
        }
    }
    // epilogue
#pragma unroll
    for (int i = 0; i < 8; ++i) {
        float out[8];
#pragma unroll
        for (int p = 0; p < 4; ++p) {
            float2 u = unpack2f(acc[i][p]);
            out[2 * p] = u.x; out[2 * p + 1] = u.y;
        }
        int row  = m0 + rbase + i;
        int coln = n0 + cbase;
        float4 o0 = make_float4(out[0] + bg_l[coln + 0], out[1] + bg_l[coln + 1],
                                out[2] + bg_l[coln + 2], out[3] + bg_l[coln + 3]);
        float4 o1 = make_float4(out[4] + bg_l[coln + 4], out[5] + bg_l[coln + 5],
                                out[6] + bg_l[coln + 6], out[7] + bg_l[coln + 7]);
        *reinterpret_cast<float4*>(&g_gx[(size_t)row * GD + coln])     = o0;
        *reinterpret_cast<float4*>(&g_gx[(size_t)row * GD + coln + 4]) = o1;
    }
}

// ---------------- 4) sLSTM scan: 16 clusters x 8 CTAs, Wh in registers ----------------
// CTA (batch b, rank r) owns d-slice [r*32, r*32+32) -> 128 gate columns
//   col(c) = g*256 + r*32 + j,  c = g*32 + j  (g: i/f/z/o)
// Each thread (256 of them): half = tid>>7 picks k-range, c = tid&127 picks column.
__global__ __cluster_dims__(CS, 1, 1) __launch_bounds__(256, 1)
void scan_kernel(const float* __restrict__ Wh_l)
{
    __shared__ __align__(16) float h_buf[2][DD];
    __shared__ float red[256];
    __shared__ float gx_sm[2][128];

    int tid  = threadIdx.x;
    int b    = blockIdx.x / CS;
    int r    = blockIdx.x % CS;
    int half = tid >> 7;
    int c    = tid & 127;
    int g    = c >> 5, j = c & 31;
    int col  = g * DD + r * SLICE + j;
    int k0   = half * 128;

    // Wh slice -> registers as packed f32x2 pairs over k
    unsigned long long WhP[64];
#pragma unroll
    for (int i = 0; i < 64; ++i)
        WhP[i] = pack2f(Wh_l[(size_t)(k0 + 2 * i) * GD + col],
                        Wh_l[(size_t)(k0 + 2 * i + 1) * GD + col]);

    // init h state buffer and first gx column set
    for (int i = tid; i < DD; i += 256) h_buf[0][i] = 0.f;
    const float* gx_base = g_gx + (size_t)b * SS * GD;
    if (tid < 128) gx_sm[0][c] = gx_base[col];

    // per-d recurrent state in warp 0
    float cst = 0.f, nst = 0.f, mst = 0.f, hin = 0.f;
    int d_idx = r * SLICE + (tid & 31);
    float* hrow = g_h + (size_t)b * SS * DD;
    if (tid < 32) hin = hrow[d_idx];   // residual input at t=0

    CLUSTER_SYNC();

    for (int t = 0; t < SS; ++t) {
        int cur = t & 1, nxt = cur ^ 1;
        float gx_next = 0.f;
        if (tid < 128 && t + 1 < SS)
            gx_next = __ldg(&gx_base[(size_t)(t + 1) * GD + col]);

        // dot: pre[col] partial = sum_{k in half} h[k] * Wh[k][col]
        const unsigned long long* h8 =
            reinterpret_cast<const unsigned long long*>(&h_buf[cur][k0]);
        unsigned long long a0 = 0ull, a1 = 0ull;
#pragma unroll
        for (int i = 0; i < 32; ++i) {
            a0 = ffma2(WhP[2 * i],     h8[2 * i],     a0);
            a1 = ffma2(WhP[2 * i + 1], h8[2 * i + 1], a1);
        }
        float2 p0 = unpack2f(a0), p1 = unpack2f(a1);
        red[tid] = (p0.x + p0.y) + (p1.x + p1.y);
        __syncthreads();

        if (tid < 128) gx_sm[nxt][c] = gx_next;   // stage next step's gx

        if (tid < 32) {
            int jj = tid;
            float ii = red[jj]      + red[jj + 128] + gx_sm[cur][jj];
            float ff = red[jj + 32] + red[jj + 160] + gx_sm[cur][jj + 32];
            float zz = red[jj + 64] + red[jj + 192] + gx_sm[cur][jj + 64];
            float oo = red[jj + 96] + red[jj + 224] + gx_sm[cur][jj + 96];

            float mn = fmaxf(ff + mst, ii);
            float ip = __expf(ii - mn);
            float fp = __expf(ff + mst - mn);
            float e2z = __expf(2.f * zz);
            float tz  = 1.f - 2.f / (e2z + 1.f);       // tanh(zz)
            cst = fp * cst + ip * tz;
            nst = fp * nst + ip;
            mst = mn;
            float sg = 1.f / (1.f + __expf(-oo));
            float hv = sg * cst / fmaxf(fabsf(nst), 1.f);

            // residual output (next layer's input / final readout)
            hrow[(size_t)t * DD + d_idx] = hin + hv;
            if (t + 1 < SS) hin = hrow[(size_t)(t + 1) * DD + d_idx];

            // broadcast new hidden value to all CTAs' h_buf[nxt]
            uint32_t laddr = smem_u32(&h_buf[nxt][d_idx]);
#pragma unroll
            for (int p = 0; p < CS; ++p) {
                uint32_t raddr;
                asm("mapa.shared::cluster.u32 %0, %1, %2;"
                    : "=r"(raddr) : "r"(laddr), "r"(p));
                asm volatile("st.shared::cluster.f32 [%0], %1;"
                             :: "r"(raddr), "f"(hv) : "memory");
            }
        }
        CLUSTER_SYNC();
    }
}

// ---------------- 5) final: out[b] = h[b, S-1, :] @ fc_W + fc_b ----------------
__global__ __launch_bounds__(DD) void final_kernel(
    const float* __restrict__ fcW, const float* __restrict__ fcb,
    float* __restrict__ out)
{
    int b = blockIdx.x, tid = threadIdx.x;
    const float* row = g_h + ((size_t)b * SS + (SS - 1)) * DD;
    __shared__ float sm[DD];
    sm[tid] = row[tid] * fcW[tid];
    __syncthreads();
    for (int o = DD / 2; o; o >>= 1) {
        if (tid < o) sm[tid] += sm[tid + o];
        __syncthreads();
    }
    if (tid == 0) out[b] = sm[0] + fcb[0];
}

// ---------------- launch ----------------
extern "C" void kernel_launch(void* const* d_in, const int* in_sizes, int n_in,
                              void* d_out, int out_size)
{
    const float* x   = (const float*)d_in[0];
    const float* tf  = (const float*)d_in[1];
    const float* inW = (const float*)d_in[2];
    const float* inb = (const float*)d_in[3];
    const float* lng = (const float*)d_in[4];
    const float* lnb = (const float*)d_in[5];
    const float* Wx  = (const float*)d_in[6];
    const float* Wh  = (const float*)d_in[7];
    const float* bg  = (const float*)d_in[8];
    const float* fcW = (const float*)d_in[9];
    const float* fcb = (const float*)d_in[10];
    float* out = (float*)d_out;

    embed_kernel<<<BB * SS, DD>>>(x, tf, inW, inb);
    for (int l = 0; l < LL; ++l) {
        ln_kernel<<<(BB * SS) / 8, 256>>>(lng + l * DD, lnb + l * DD);
        gemm_kernel<<<dim3(GD / GBN, (BB * SS) / GBM), 256>>>(
            Wx + (size_t)l * DD * GD, bg + (size_t)l * GD);
        scan_kernel<<<BB * CS, 256>>>(Wh + (size_t)l * DD * GD);
    }
    final_kernel<<<BB, DD>>>(fcW, fcb, out);
}

// round 5
// speedup vs baseline: 1.2966x; 1.2966x over previous
#include <cuda_runtime.h>
#include <cuda_bf16.h>
#include <cstdint>
#include <cstddef>

// Problem dims (fixed)
#define BB 16
#define SS 2048
#define DD 256
#define GD 1024      // 4*D
#define LL 4
#define CS 8         // cluster size (CTAs per batch recurrence)
#define SLICE 32     // D / CS

// ---------------- scratch (static device globals; no allocations) ----------------
__device__ float g_h [BB * SS * DD];   // hidden / residual stream  (32 MB)
__device__ float g_xn[BB * SS * DD];   // layernormed activations   (32 MB)
__device__ float g_gx[(size_t)BB * SS * GD];  // gate preactivations (128 MB)

// ---------------- f32x2 packed helpers ----------------
__device__ __forceinline__ unsigned long long pack2f(float lo, float hi) {
    unsigned long long r;
    asm("mov.b64 %0, {%1, %2};" : "=l"(r) : "f"(lo), "f"(hi));
    return r;
}
__device__ __forceinline__ float2 unpack2f(unsigned long long v) {
    float2 r;
    asm("mov.b64 {%0, %1}, %2;" : "=f"(r.x), "=f"(r.y) : "l"(v));
    return r;
}
__device__ __forceinline__ unsigned long long ffma2(unsigned long long a,
                                                    unsigned long long b,
                                                    unsigned long long c) {
    unsigned long long d;
    asm("fma.rn.f32x2 %0, %1, %2, %3;" : "=l"(d) : "l"(a), "l"(b), "l"(c));
    return d;
}
__device__ __forceinline__ uint32_t smem_u32(const void* p) {
    uint32_t a;
    asm("{ .reg .u64 t; cvta.to.shared.u64 t, %1; cvt.u32.u64 %0, t; }"
        : "=r"(a) : "l"(p));
    return a;
}
__device__ __forceinline__ float tanh_approx(float x) {
    float y;
    asm("tanh.approx.f32 %0, %1;" : "=f"(y) : "f"(x));
    return y;
}
#define CLUSTER_SYNC() do {                                          \
    asm volatile("barrier.cluster.arrive.aligned;" ::: "memory");    \
    asm volatile("barrier.cluster.wait.aligned;"   ::: "memory");    \
} while (0)

// tagged DSMEM exchange primitives
__device__ __forceinline__ void st_peer_b64(uint32_t raddr, unsigned long long v) {
    asm volatile("st.relaxed.cluster.shared::cluster.b64 [%0], %1;"
                 :: "r"(raddr), "l"(v) : "memory");
}
__device__ __forceinline__ unsigned long long ld_tag_b64(uint32_t addr) {
    unsigned long long v;
    asm volatile("ld.relaxed.cluster.shared::cta.b64 %0, [%1];"
                 : "=l"(v) : "r"(addr) : "memory");
    return v;
}

// ---------------- 1) embedding ----------------
__global__ __launch_bounds__(DD) void embed_kernel(
    const float* __restrict__ x, const float* __restrict__ tf,
    const float* __restrict__ inW, const float* __restrict__ inb)
{
    int row = blockIdx.x;
    int d   = threadIdx.x;
    float xv  = x[row];
    float acc = inb[d] + xv * inW[d];
#pragma unroll
    for (int f = 0; f < 6; ++f)
        acc += tf[row * 6 + f] * inW[(1 + f) * DD + d];
    g_h[(size_t)row * DD + d] = acc;
}

// ---------------- 2) layernorm ----------------
__global__ __launch_bounds__(256) void ln_kernel(
    const float* __restrict__ gam, const float* __restrict__ bet)
{
    int warp = (blockIdx.x * blockDim.x + threadIdx.x) >> 5;
    int lane = threadIdx.x & 31;
    if (warp >= BB * SS) return;
    const float* row = g_h + (size_t)warp * DD;
    float v[8], s = 0.f, s2 = 0.f;
#pragma unroll
    for (int i = 0; i < 8; ++i) {
        v[i] = row[lane + i * 32];
        s  += v[i];
        s2 += v[i] * v[i];
    }
#pragma unroll
    for (int o = 16; o; o >>= 1) {
        s  += __shfl_xor_sync(0xffffffffu, s,  o);
        s2 += __shfl_xor_sync(0xffffffffu, s2, o);
    }
    float mu  = s * (1.f / DD);
    float var = s2 * (1.f / DD) - mu * mu;
    float rs  = rsqrtf(var + 1e-5f);
    float* orow = g_xn + (size_t)warp * DD;
#pragma unroll
    for (int i = 0; i < 8; ++i) {
        int d = lane + i * 32;
        orow[d] = (v[i] - mu) * rs * gam[d] + bet[d];
    }
}

// ---------------- 3) gx GEMM ----------------
#define GBM 128
#define GBN 128
#define GBK 16
__global__ __launch_bounds__(256) void gemm_kernel(
    const float* __restrict__ Wx_l, const float* __restrict__ bg_l)
{
    __shared__ __align__(16) float As[GBK][GBM];
    __shared__ __align__(16) float Bs[GBK][GBN];
    int tid = threadIdx.x;
    int m0  = blockIdx.y * GBM;
    int n0  = blockIdx.x * GBN;
    int ty = tid >> 4, tx = tid & 15;
    int rbase = ty * 8, cbase = tx * 8;

    unsigned long long acc[8][4];
#pragma unroll
    for (int i = 0; i < 8; ++i)
#pragma unroll
        for (int p = 0; p < 4; ++p) acc[i][p] = 0ull;

    for (int k0 = 0; k0 < DD; k0 += GBK) {
        __syncthreads();
#pragma unroll
        for (int q = 0; q < 2; ++q) {
            int f = tid * 2 + q;
            int arow = f >> 2, ac4 = f & 3;
            float4 av = *reinterpret_cast<const float4*>(
                &g_xn[(size_t)(m0 + arow) * DD + k0 + ac4 * 4]);
            As[ac4 * 4 + 0][arow] = av.x;
            As[ac4 * 4 + 1][arow] = av.y;
            As[ac4 * 4 + 2][arow] = av.z;
            As[ac4 * 4 + 3][arow] = av.w;
            int brow = f >> 5, bc4 = f & 31;
            *reinterpret_cast<float4*>(&Bs[brow][bc4 * 4]) =
                *reinterpret_cast<const float4*>(
                    &Wx_l[(size_t)(k0 + brow) * GD + n0 + bc4 * 4]);
        }
        __syncthreads();
#pragma unroll
        for (int kk = 0; kk < GBK; ++kk) {
            float4 a0 = *reinterpret_cast<const float4*>(&As[kk][rbase]);
            float4 a1 = *reinterpret_cast<const float4*>(&As[kk][rbase + 4]);
            float4 b0 = *reinterpret_cast<const float4*>(&Bs[kk][cbase]);
            float4 b1 = *reinterpret_cast<const float4*>(&Bs[kk][cbase + 4]);
            unsigned long long bp[4] = { pack2f(b0.x, b0.y), pack2f(b0.z, b0.w),
                                         pack2f(b1.x, b1.y), pack2f(b1.z, b1.w) };
            float aa[8] = { a0.x, a0.y, a0.z, a0.w, a1.x, a1.y, a1.z, a1.w };
#pragma unroll
            for (int i = 0; i < 8; ++i) {
                unsigned long long ad = pack2f(aa[i], aa[i]);
#pragma unroll
                for (int p = 0; p < 4; ++p) acc[i][p] = ffma2(ad, bp[p], acc[i][p]);
            }
        }
    }
#pragma unroll
    for (int i = 0; i < 8; ++i) {
        float out[8];
#pragma unroll
        for (int p = 0; p < 4; ++p) {
            float2 u = unpack2f(acc[i][p]);
            out[2 * p] = u.x; out[2 * p + 1] = u.y;
        }
        int row  = m0 + rbase + i;
        int coln = n0 + cbase;
        float4 o0 = make_float4(out[0] + bg_l[coln + 0], out[1] + bg_l[coln + 1],
                                out[2] + bg_l[coln + 2], out[3] + bg_l[coln + 3]);
        float4 o1 = make_float4(out[4] + bg_l[coln + 4], out[5] + bg_l[coln + 5],
                                out[6] + bg_l[coln + 6], out[7] + bg_l[coln + 7]);
        *reinterpret_cast<float4*>(&g_gx[(size_t)row * GD + coln])     = o0;
        *reinterpret_cast<float4*>(&g_gx[(size_t)row * GD + coln + 4]) = o1;
    }
}

// ---------------- 4) sLSTM scan: barrier-free tagged DSMEM recurrence ----------------
// 16 clusters x 8 CTAs. CTA (b, r) owns gate cols {g*256 + r*32 + j}.
// Each h value is exchanged as one 8-byte atom: (tag<<32)|f32bits, double-buffered.
// Consumers spin on their own smem entry (1 entry per thread), no cluster barriers
// in the steady state.
__global__ __cluster_dims__(CS, 1, 1) __launch_bounds__(256, 1)
void scan_kernel(const float* __restrict__ Wh_l)
{
    __shared__ __align__(16) unsigned long long h_tag[2][DD]; // tagged exchange buffers
    __shared__ __align__(16) float h_pack[DD];                // packed h for the dot
    __shared__ float red[256];
    __shared__ float gx_sm[2][128];

    int tid  = threadIdx.x;
    int b    = blockIdx.x / CS;
    int r    = blockIdx.x % CS;
    int half = tid >> 7;
    int c    = tid & 127;
    int g    = c >> 5, j = c & 31;
    int col  = g * DD + r * SLICE + j;
    int k0   = half * 128;
    int d_idx = r * SLICE + (tid & 31);

    // Wh slice -> registers as packed f32x2 pairs over k
    unsigned long long WhP[64];
#pragma unroll
    for (int i = 0; i < 64; ++i)
        WhP[i] = pack2f(Wh_l[(size_t)(k0 + 2 * i) * GD + col],
                        Wh_l[(size_t)(k0 + 2 * i + 1) * GD + col]);

    // init exchange buffers (stale smem from a previous launch could alias tags)
    h_tag[0][tid] = 0ull;
    h_tag[1][tid] = 0ull;
    h_pack[tid]   = 0.f;

    const float* gx_base = g_gx + (size_t)b * SS * GD;
    if (tid < 128) gx_sm[0][c] = gx_base[col];

    // precompute peer addresses of h_tag[0][d_idx] in each CTA's smem
    uint32_t peer_addr[CS];
    {
        uint32_t laddr = smem_u32(&h_tag[0][d_idx]);
#pragma unroll
        for (int p = 0; p < CS; ++p)
            asm("mapa.shared::cluster.u32 %0, %1, %2;"
                : "=r"(peer_addr[p]) : "r"(laddr), "r"(p));
    }

    float cst = 0.f, nst = 0.f, mst = 0.f, hin = 0.f, hin_next = 0.f;
    float* hrow = g_h + (size_t)b * SS * DD;
    if (tid < 32) hin = hrow[d_idx];

    __syncthreads();
    CLUSTER_SYNC();   // one-time: zeroed tag buffers visible before anyone stores

    uint32_t myslot = smem_u32(&h_tag[0][tid]);

    for (int t = 0; t < SS; ++t) {
        int cur = t & 1;

        // 1) spin on this thread's tagged entry until step-t value arrives
        if (t > 0) {
            uint32_t a = myslot + (uint32_t)cur * (DD * 8);
            unsigned long long v = ld_tag_b64(a);
            while ((uint32_t)(v >> 32) != (uint32_t)t) v = ld_tag_b64(a);
            h_pack[tid] = __uint_as_float((uint32_t)v);
        }

        // prefetches for t+1 (independent; overlap with spin/sync)
        float gx_next = 0.f;
        if (tid < 128 && t + 1 < SS)
            gx_next = __ldg(&gx_base[(size_t)(t + 1) * GD + col]);
        if (tid < 32 && t + 1 < SS)
            hin_next = __ldg(&hrow[(size_t)(t + 1) * DD + d_idx]);

        __syncthreads();   // h_pack complete; also protects vs next-step overwrite

        // 2) dot: partial over this thread's k-half (broadcast LDS.128, 2 chains)
        const ulonglong2* h16 = reinterpret_cast<const ulonglong2*>(&h_pack[k0]);
        unsigned long long a0 = 0ull, a1 = 0ull;
#pragma unroll
        for (int i = 0; i < 32; ++i) {
            ulonglong2 hv2 = h16[i];
            a0 = ffma2(WhP[2 * i],     hv2.x, a0);
            a1 = ffma2(WhP[2 * i + 1], hv2.y, a1);
        }
        float2 p0 = unpack2f(a0), p1 = unpack2f(a1);
        red[tid] = (p0.x + p0.y) + (p1.x + p1.y);
        if (tid < 128) gx_sm[(t + 1) & 1][c] = gx_next;   // stage next gx
        __syncthreads();

        // 3) gates + state update + broadcast (warp 0)
        if (tid < 32) {
            int jj = tid;
            float ii = red[jj]      + red[jj + 128] + gx_sm[cur][jj];
            float ff = red[jj + 32] + red[jj + 160] + gx_sm[cur][jj + 32];
            float zz = red[jj + 64] + red[jj + 192] + gx_sm[cur][jj + 64];
            float oo = red[jj + 96] + red[jj + 224] + gx_sm[cur][jj + 96];

            float mn = fmaxf(ff + mst, ii);
            float ip = __expf(ii - mn);
            float fp = __expf(ff + mst - mn);
            float tz = tanh_approx(zz);
            cst = fp * cst + ip * tz;
            nst = fp * nst + ip;
            mst = mn;
            float sg = 0.5f + 0.5f * tanh_approx(0.5f * oo);  // sigmoid
            float hv = sg * cst / fmaxf(fabsf(nst), 1.f);

            if (t + 1 < SS) {
                unsigned long long val =
                    ((unsigned long long)(uint32_t)(t + 1) << 32) |
                    (unsigned long long)__float_as_uint(hv);
                uint32_t off = (uint32_t)((t + 1) & 1) * (DD * 8);
#pragma unroll
                for (int p = 0; p < CS; ++p)
                    st_peer_b64(peer_addr[p] + off, val);
            }

            // residual stream write (fire-and-forget; consumer = next kernel)
            hrow[(size_t)t * DD + d_idx] = hin + hv;
            hin = hin_next;
        }
    }
}

// ---------------- 5) final ----------------
__global__ __launch_bounds__(DD) void final_kernel(
    const float* __restrict__ fcW, const float* __restrict__ fcb,
    float* __restrict__ out)
{
    int b = blockIdx.x, tid = threadIdx.x;
    const float* row = g_h + ((size_t)b * SS + (SS - 1)) * DD;
    __shared__ float sm[DD];
    sm[tid] = row[tid] * fcW[tid];
    __syncthreads();
    for (int o = DD / 2; o; o >>= 1) {
        if (tid < o) sm[tid] += sm[tid + o];
        __syncthreads();
    }
    if (tid == 0) out[b] = sm[0] + fcb[0];
}

// ---------------- launch ----------------
extern "C" void kernel_launch(void* const* d_in, const int* in_sizes, int n_in,
                              void* d_out, int out_size)
{
    const float* x   = (const float*)d_in[0];
    const float* tf  = (const float*)d_in[1];
    const float* inW = (const float*)d_in[2];
    const float* inb = (const float*)d_in[3];
    const float* lng = (const float*)d_in[4];
    const float* lnb = (const float*)d_in[5];
    const float* Wx  = (const float*)d_in[6];
    const float* Wh  = (const float*)d_in[7];
    const float* bg  = (const float*)d_in[8];
    const float* fcW = (const float*)d_in[9];
    const float* fcb = (const float*)d_in[10];
    float* out = (float*)d_out;

    embed_kernel<<<BB * SS, DD>>>(x, tf, inW, inb);
    for (int l = 0; l < LL; ++l) {
        ln_kernel<<<(BB * SS) / 8, 256>>>(lng + l * DD, lnb + l * DD);
        gemm_kernel<<<dim3(GD / GBN, (BB * SS) / GBM), 256>>>(
            Wx + (size_t)l * DD * GD, bg + (size_t)l * GD);
        scan_kernel<<<BB * CS, 256>>>(Wh + (size_t)l * DD * GD);
    }
    final_kernel<<<BB, DD>>>(fcW, fcb, out);
}

// round 6
// speedup vs baseline: 1.7131x; 1.3212x over previous
#include <cuda_runtime.h>
#include <cuda_bf16.h>
#include <cstdint>
#include <cstddef>

// Problem dims (fixed)
#define BB 16
#define SS 2048
#define DD 256
#define GD 1024      // 4*D
#define LL 4
#define CS 8         // cluster size (CTAs per batch recurrence)
#define SLICE 32     // D / CS

// ---------------- scratch (static device globals; no allocations) ----------------
__device__ float g_h [BB * SS * DD];   // hidden / residual stream  (32 MB)
__device__ float g_xn[BB * SS * DD];   // layernormed activations   (32 MB)
__device__ float g_gx[(size_t)BB * SS * GD];  // gate preactivations (128 MB)

// ---------------- f32x2 packed helpers ----------------
__device__ __forceinline__ unsigned long long pack2f(float lo, float hi) {
    unsigned long long r;
    asm("mov.b64 %0, {%1, %2};" : "=l"(r) : "f"(lo), "f"(hi));
    return r;
}
__device__ __forceinline__ float2 unpack2f(unsigned long long v) {
    float2 r;
    asm("mov.b64 {%0, %1}, %2;" : "=f"(r.x), "=f"(r.y) : "l"(v));
    return r;
}
__device__ __forceinline__ unsigned long long ffma2(unsigned long long a,
                                                    unsigned long long b,
                                                    unsigned long long c) {
    unsigned long long d;
    asm("fma.rn.f32x2 %0, %1, %2, %3;" : "=l"(d) : "l"(a), "l"(b), "l"(c));
    return d;
}
__device__ __forceinline__ uint32_t smem_u32(const void* p) {
    uint32_t a;
    asm("{ .reg .u64 t; cvta.to.shared.u64 t, %1; cvt.u32.u64 %0, t; }"
        : "=r"(a) : "l"(p));
    return a;
}
__device__ __forceinline__ float tanh_approx(float x) {
    float y;
    asm("tanh.approx.f32 %0, %1;" : "=f"(y) : "f"(x));
    return y;
}
#define CLUSTER_SYNC() do {                                          \
    asm volatile("barrier.cluster.arrive.aligned;" ::: "memory");    \
    asm volatile("barrier.cluster.wait.aligned;"   ::: "memory");    \
} while (0)

// tagged DSMEM exchange primitives
__device__ __forceinline__ void st_peer_b64(uint32_t raddr, unsigned long long v) {
    asm volatile("st.relaxed.cluster.shared::cluster.b64 [%0], %1;"
                 :: "r"(raddr), "l"(v) : "memory");
}
__device__ __forceinline__ unsigned long long ld_tag_b64(uint32_t addr) {
    unsigned long long v;
    asm volatile("ld.relaxed.cluster.shared::cta.b64 %0, [%1];"
                 : "=l"(v) : "r"(addr) : "memory");
    return v;
}
// cp.async 16B (LDGSTS) helpers
__device__ __forceinline__ void cp_async16(void* smem_dst, const void* gmem_src) {
    uint32_t d = smem_u32(smem_dst);
    asm volatile("cp.async.cg.shared.global [%0], [%1], 16;"
                 :: "r"(d), "l"(gmem_src) : "memory");
}
#define CP_COMMIT() asm volatile("cp.async.commit_group;" ::: "memory")
#define CP_WAIT2()  asm volatile("cp.async.wait_group 2;"  ::: "memory")

// ---------------- 1) embedding ----------------
__global__ __launch_bounds__(DD) void embed_kernel(
    const float* __restrict__ x, const float* __restrict__ tf,
    const float* __restrict__ inW, const float* __restrict__ inb)
{
    int row = blockIdx.x;
    int d   = threadIdx.x;
    float xv  = x[row];
    float acc = inb[d] + xv * inW[d];
#pragma unroll
    for (int f = 0; f < 6; ++f)
        acc += tf[row * 6 + f] * inW[(1 + f) * DD + d];
    g_h[(size_t)row * DD + d] = acc;
}

// ---------------- 2) layernorm ----------------
__global__ __launch_bounds__(256) void ln_kernel(
    const float* __restrict__ gam, const float* __restrict__ bet)
{
    int warp = (blockIdx.x * blockDim.x + threadIdx.x) >> 5;
    int lane = threadIdx.x & 31;
    if (warp >= BB * SS) return;
    const float* row = g_h + (size_t)warp * DD;
    float v[8], s = 0.f, s2 = 0.f;
#pragma unroll
    for (int i = 0; i < 8; ++i) {
        v[i] = row[lane + i * 32];
        s  += v[i];
        s2 += v[i] * v[i];
    }
#pragma unroll
    for (int o = 16; o; o >>= 1) {
        s  += __shfl_xor_sync(0xffffffffu, s,  o);
        s2 += __shfl_xor_sync(0xffffffffu, s2, o);
    }
    float mu  = s * (1.f / DD);
    float var = s2 * (1.f / DD) - mu * mu;
    float rs  = rsqrtf(var + 1e-5f);
    float* orow = g_xn + (size_t)warp * DD;
#pragma unroll
    for (int i = 0; i < 8; ++i) {
        int d = lane + i * 32;
        orow[d] = (v[i] - mu) * rs * gam[d] + bet[d];
    }
}

// ---------------- 3) gx GEMM ----------------
#define GBM 128
#define GBN 128
#define GBK 16
__global__ __launch_bounds__(256) void gemm_kernel(
    const float* __restrict__ Wx_l, const float* __restrict__ bg_l)
{
    __shared__ __align__(16) float As[GBK][GBM];
    __shared__ __align__(16) float Bs[GBK][GBN];
    int tid = threadIdx.x;
    int m0  = blockIdx.y * GBM;
    int n0  = blockIdx.x * GBN;
    int ty = tid >> 4, tx = tid & 15;
    int rbase = ty * 8, cbase = tx * 8;

    unsigned long long acc[8][4];
#pragma unroll
    for (int i = 0; i < 8; ++i)
#pragma unroll
        for (int p = 0; p < 4; ++p) acc[i][p] = 0ull;

    for (int k0 = 0; k0 < DD; k0 += GBK) {
        __syncthreads();
#pragma unroll
        for (int q = 0; q < 2; ++q) {
            int f = tid * 2 + q;
            int arow = f >> 2, ac4 = f & 3;
            float4 av = *reinterpret_cast<const float4*>(
                &g_xn[(size_t)(m0 + arow) * DD + k0 + ac4 * 4]);
            As[ac4 * 4 + 0][arow] = av.x;
            As[ac4 * 4 + 1][arow] = av.y;
            As[ac4 * 4 + 2][arow] = av.z;
            As[ac4 * 4 + 3][arow] = av.w;
            int brow = f >> 5, bc4 = f & 31;
            *reinterpret_cast<float4*>(&Bs[brow][bc4 * 4]) =
                *reinterpret_cast<const float4*>(
                    &Wx_l[(size_t)(k0 + brow) * GD + n0 + bc4 * 4]);
        }
        __syncthreads();
#pragma unroll
        for (int kk = 0; kk < GBK; ++kk) {
            float4 a0 = *reinterpret_cast<const float4*>(&As[kk][rbase]);
            float4 a1 = *reinterpret_cast<const float4*>(&As[kk][rbase + 4]);
            float4 b0 = *reinterpret_cast<const float4*>(&Bs[kk][cbase]);
            float4 b1 = *reinterpret_cast<const float4*>(&Bs[kk][cbase + 4]);
            unsigned long long bp[4] = { pack2f(b0.x, b0.y), pack2f(b0.z, b0.w),
                                         pack2f(b1.x, b1.y), pack2f(b1.z, b1.w) };
            float aa[8] = { a0.x, a0.y, a0.z, a0.w, a1.x, a1.y, a1.z, a1.w };
#pragma unroll
            for (int i = 0; i < 8; ++i) {
                unsigned long long ad = pack2f(aa[i], aa[i]);
#pragma unroll
                for (int p = 0; p < 4; ++p) acc[i][p] = ffma2(ad, bp[p], acc[i][p]);
            }
        }
    }
#pragma unroll
    for (int i = 0; i < 8; ++i) {
        float out[8];
#pragma unroll
        for (int p = 0; p < 4; ++p) {
            float2 u = unpack2f(acc[i][p]);
            out[2 * p] = u.x; out[2 * p + 1] = u.y;
        }
        int row  = m0 + rbase + i;
        int coln = n0 + cbase;
        float4 o0 = make_float4(out[0] + bg_l[coln + 0], out[1] + bg_l[coln + 1],
                                out[2] + bg_l[coln + 2], out[3] + bg_l[coln + 3]);
        float4 o1 = make_float4(out[4] + bg_l[coln + 4], out[5] + bg_l[coln + 5],
                                out[6] + bg_l[coln + 6], out[7] + bg_l[coln + 7]);
        *reinterpret_cast<float4*>(&g_gx[(size_t)row * GD + coln])     = o0;
        *reinterpret_cast<float4*>(&g_gx[(size_t)row * GD + coln + 4]) = o1;
    }
}

// ---------------- 4) sLSTM scan: tagged DSMEM recurrence + cp.async rings ----------------
// 16 clusters x 8 CTAs. CTA (b, r) owns gate cols {g*256 + r*32 + j}.
// h exchanged as (tag<<32|f32) atoms, double-buffered (skew bounded at 1 step by
// the tag causality chain). gx + residual rows stream through 4-slot smem rings
// filled at distance 3 by cp.async from warps 1/2 — DRAM latency off the
// critical path. Ring slot reuse distance >= 3 steps, protected by the step bars.
__global__ __cluster_dims__(CS, 1, 1) __launch_bounds__(256, 1)
void scan_kernel(const float* __restrict__ Wh_l)
{
    __shared__ __align__(16) unsigned long long h_tag[2][DD]; // tagged exchange buffers
    __shared__ __align__(16) float h_pack[DD];                // packed h for the dot
    __shared__ __align__(16) float red[256];
    __shared__ __align__(16) float gx_ring[4][128];           // gate preacts, dist-3
    __shared__ __align__(16) float hres_ring[4][SLICE];       // residual rows, dist-3

    int tid  = threadIdx.x;
    int b    = blockIdx.x / CS;
    int r    = blockIdx.x % CS;
    int half = tid >> 7;
    int c    = tid & 127;
    int g    = c >> 5, j = c & 31;
    int col  = g * DD + r * SLICE + j;
    int k0   = half * 128;
    int lane = tid & 31;
    int wid  = tid >> 5;
    int d_idx = r * SLICE + lane;

    // Wh slice -> registers as packed f32x2 pairs over k
    unsigned long long WhP[64];
#pragma unroll
    for (int i = 0; i < 64; ++i)
        WhP[i] = pack2f(Wh_l[(size_t)(k0 + 2 * i) * GD + col],
                        Wh_l[(size_t)(k0 + 2 * i + 1) * GD + col]);

    // init exchange buffers
    h_tag[0][tid] = 0ull;
    h_tag[1][tid] = 0ull;
    h_pack[tid]   = 0.f;

    const float* gx_base = g_gx + (size_t)b * SS * GD;
    float*       hrow    = g_h  + (size_t)b * SS * DD;

    // preload ring slots for steps 0..2
    if (tid < 128)
#pragma unroll
        for (int s = 0; s < 3; ++s)
            gx_ring[s][c] = gx_base[(size_t)s * GD + col];
    if (tid < 32)
#pragma unroll
        for (int s = 0; s < 3; ++s)
            hres_ring[s][lane] = hrow[(size_t)s * DD + d_idx];

    // precompute peer addresses of h_tag[0][d_idx] in each CTA's smem
    uint32_t peer_addr[CS];
    {
        uint32_t laddr = smem_u32(&h_tag[0][d_idx]);
#pragma unroll
        for (int p = 0; p < CS; ++p)
            asm("mapa.shared::cluster.u32 %0, %1, %2;"
                : "=r"(peer_addr[p]) : "r"(laddr), "r"(p));
    }

    float cst = 0.f, nst = 0.f, mst = 0.f;

    __syncthreads();
    CLUSTER_SYNC();   // one-time: zeroed tag buffers visible before anyone stores

    uint32_t myslot = smem_u32(&h_tag[0][tid]);

    for (int t = 0; t < SS; ++t) {
        int cur = t & 1;

        // 1) spin on this thread's tagged entry until step-t value arrives
        if (t > 0) {
            uint32_t a = myslot + (uint32_t)cur * (DD * 8);
            unsigned long long v = ld_tag_b64(a);
            while ((uint32_t)(v >> 32) != (uint32_t)t) v = ld_tag_b64(a);
            h_pack[tid] = __uint_as_float((uint32_t)v);
        }
        __syncthreads();   // bar1: h_pack complete (also guards slot overwrite)

        // 2) dot: partial over this thread's k-half (broadcast LDS.128, 2 chains)
        const ulonglong2* h16 = reinterpret_cast<const ulonglong2*>(&h_pack[k0]);
        unsigned long long a0 = 0ull, a1 = 0ull;
#pragma unroll
        for (int i = 0; i < 32; ++i) {
            ulonglong2 hv2 = h16[i];
            a0 = ffma2(WhP[2 * i],     hv2.x, a0);
            a1 = ffma2(WhP[2 * i + 1], hv2.y, a1);
        }
        float2 p0 = unpack2f(a0), p1 = unpack2f(a1);
        red[tid] = (p0.x + p0.y) + (p1.x + p1.y);

        // 2b) async prefetch for step t+3 (off critical path; no reg dependency)
        if (wid == 1) {
            int tp = t + 3;
            if (tp < SS) {
                int gg = lane >> 3, ch = lane & 7;
                cp_async16(&gx_ring[tp & 3][gg * 32 + ch * 4],
                           gx_base + (size_t)tp * GD + gg * DD + r * SLICE + ch * 4);
            }
            CP_COMMIT();
            CP_WAIT2();
        } else if (wid == 2) {
            int tp = t + 3;
            if (tp < SS && lane < 8)
                cp_async16(&hres_ring[tp & 3][lane * 4],
                           hrow + (size_t)tp * DD + r * SLICE + lane * 4);
            CP_COMMIT();
            CP_WAIT2();
        }
        __syncthreads();   // bar2: red + ring slots published

        // 3) gates + state update + broadcast (warp 0)
        if (tid < 32) {
            int jj = tid;
            const float* gxs = gx_ring[t & 3];
            float ii = red[jj]      + red[jj + 128] + gxs[jj];
            float ff = red[jj + 32] + red[jj + 160] + gxs[jj + 32];
            float zz = red[jj + 64] + red[jj + 192] + gxs[jj + 64];
            float oo = red[jj + 96] + red[jj + 224] + gxs[jj + 96];

            float mn = fmaxf(ff + mst, ii);
            float ip = __expf(ii - mn);
            float fp = __expf(ff + mst - mn);
            float tz = tanh_approx(zz);
            cst = fp * cst + ip * tz;
            nst = fp * nst + ip;
            mst = mn;
            float sg = 0.5f + 0.5f * tanh_approx(0.5f * oo);  // sigmoid
            float hv = sg * cst / fmaxf(fabsf(nst), 1.f);

            if (t + 1 < SS) {
                unsigned long long val =
                    ((unsigned long long)(uint32_t)(t + 1) << 32) |
                    (unsigned long long)__float_as_uint(hv);
                uint32_t off = (uint32_t)((t + 1) & 1) * (DD * 8);
#pragma unroll
                for (int p = 0; p < CS; ++p)
                    st_peer_b64(peer_addr[p] + off, val);
            }

            // residual stream write (fire-and-forget; consumer = next kernel)
            hrow[(size_t)t * DD + d_idx] = hres_ring[t & 3][lane] + hv;
        }
    }
}

// ---------------- 5) final ----------------
__global__ __launch_bounds__(DD) void final_kernel(
    const float* __restrict__ fcW, const float* __restrict__ fcb,
    float* __restrict__ out)
{
    int b = blockIdx.x, tid = threadIdx.x;
    const float* row = g_h + ((size_t)b * SS + (SS - 1)) * DD;
    __shared__ float sm[DD];
    sm[tid] = row[tid] * fcW[tid];
    __syncthreads();
    for (int o = DD / 2; o; o >>= 1) {
        if (tid < o) sm[tid] += sm[tid + o];
        __syncthreads();
    }
    if (tid == 0) out[b] = sm[0] + fcb[0];
}

// ---------------- launch ----------------
extern "C" void kernel_launch(void* const* d_in, const int* in_sizes, int n_in,
                              void* d_out, int out_size)
{
    const float* x   = (const float*)d_in[0];
    const float* tf  = (const float*)d_in[1];
    const float* inW = (const float*)d_in[2];
    const float* inb = (const float*)d_in[3];
    const float* lng = (const float*)d_in[4];
    const float* lnb = (const float*)d_in[5];
    const float* Wx  = (const float*)d_in[6];
    const float* Wh  = (const float*)d_in[7];
    const float* bg  = (const float*)d_in[8];
    const float* fcW = (const float*)d_in[9];
    const float* fcb = (const float*)d_in[10];
    float* out = (float*)d_out;

    embed_kernel<<<BB * SS, DD>>>(x, tf, inW, inb);
    for (int l = 0; l < LL; ++l) {
        ln_kernel<<<(BB * SS) / 8, 256>>>(lng + l * DD, lnb + l * DD);
        gemm_kernel<<<dim3(GD / GBN, (BB * SS) / GBM), 256>>>(
            Wx + (size_t)l * DD * GD, bg + (size_t)l * GD);
        scan_kernel<<<BB * CS, 256>>>(Wh + (size_t)l * DD * GD);
    }
    final_kernel<<<BB, DD>>>(fcW, fcb, out);
}